// round 10
// baseline (speedup 1.0000x reference)
#include <cuda_runtime.h>
#include <math.h>

// FLIF fractional LIF — round 10.
// R5 structure (2 neurons/warp, 1024 warps) + PRE-SCATTER 1-step look-ahead:
//   at top of step n, bcN = shfl(lane0 M[(RR+1)%12])   (pre-scatter: deltas<=n-1)
//   after delta_n:    memF_next = w1*delta_n + bcN     (local, completes dest n+1)
// The consume shfl leaves the loop-carried chain entirely; chain = 4 local ops.
// Unlike R6, the look-ahead reads PRE-scatter, so the shfl has no dependence on
// this step's 12-FMA burst and ptxas can hoist it a full step ahead of its use.

#define T_STEPS 384
typedef unsigned long long u64;

__device__ __forceinline__ u64 pack2(float x, float y) {
    u64 r; asm("mov.b64 %0, {%1, %2};" : "=l"(r) : "f"(x), "f"(y)); return r;
}
__device__ __forceinline__ void unpack2(u64 a, float& x, float& y) {
    asm("mov.b64 {%0, %1}, %2;" : "=f"(x), "=f"(y) : "l"(a));
}
__device__ __forceinline__ u64 fma2(u64 a, u64 b, u64 c) {
    u64 d; asm("fma.rn.f32x2 %0, %1, %2, %3;" : "=l"(d) : "l"(a), "l"(b), "l"(c)); return d;
}
__device__ __forceinline__ u64 add2(u64 a, u64 b) {
    u64 d; asm("add.rn.f32x2 %0, %1, %2;" : "=l"(d) : "l"(a), "l"(b)); return d;
}

struct St {
    u64 M[12];      // negated-memory accumulators (cyclic by age)
    u64 wrn[12];    // wrn[m] = (-wr[12*lane+m+1]) packed in both halves
    u64 w1n;        // (-wr[1], -wr[1])  uniform
    u64 cA, cG, cC; // (-1.75,-1.75), (-0.025,-0.025), (COEF,COEF)
    u64 memF;       // resolved negated memory for the CURRENT step
    u64 V2;
    float Vlo, Vhi;
    bool is0, is31;
    int lnext;
};

// One uniform step for n >= 2.  RR = n % 12 (compile-time).
template<int RR>
__device__ __forceinline__ void step(St& s, const u64* __restrict__ inw,
                                     u64* __restrict__ trcw, int idx)
{
    // Both shfls at the TOP: operands depend only on step n-1's scatter.
    u64 bcN = __shfl_sync(0xffffffffu, s.M[(RR + 1) % 12], 0);  // dest n+1, pre-scatter
    u64 tmp = __shfl_sync(0xffffffffu, s.M[RR], s.lnext);       // handoff lane+1 -> lane

    u64 a2  = add2(inw[idx], s.cA);          // In - 1.75
    u64 t2  = fma2(s.V2, s.cG, a2);          // -0.025*V + In - 1.75
    u64 u2  = fma2(t2, s.cC, s.V2);          // COEF*(...) + V
    u64 vp2 = add2(u2, s.memF);              // minus memory (memF negated)

    float vpl, vph; unpack2(vp2, vpl, vph);
    float vnl = vpl - ((s.Vlo > -50.0f) ? 20.0f : 0.0f);  // spike uses PREV V
    float vnh = vph - ((s.Vhi > -50.0f) ? 20.0f : 0.0f);
    u64 d2 = pack2(vnl - s.Vlo, vnh - s.Vhi);             // delta_n

    // complete dest n+1 locally: bcN (deltas<=n-1) + wr1*delta_n
    s.memF = fma2(s.w1n, d2, bcN);

    // cyclic tail refill + scatter (unchanged from R5)
    s.M[RR] = s.is31 ? 0ull : tmp;
#pragma unroll
    for (int j = 0; j < 12; ++j)
        s.M[j] = fma2(s.wrn[(j + 11 - RR) % 12], d2, s.M[j]);

    if (s.is0) trcw[idx] = pack2(vnl, vnh);
    s.Vlo = vnl; s.Vhi = vnh; s.V2 = pack2(vnl, vnh);
}

__global__ __launch_bounds__(32) void flif_kernel(
    const float* __restrict__ I,    // [S, T]
    const float* __restrict__ Wt,   // weights, length Wlen
    float* __restrict__ out,        // [2, S, T]: spikes then trace
    int S, int Wlen, float COEF)
{
    __shared__ u64 in_sh[T_STEPS];
    __shared__ u64 trc_sh[T_STEPS];

    const int lane = threadIdx.x & 31;
    const int pair = blockIdx.x;
    const int sA = pair * 2, sB = sA + 1;

    const float* rowA = I + (size_t)sA * T_STEPS;
    const float* rowB = I + (size_t)sB * T_STEPS;
    for (int t = lane; t < T_STEPS; t += 32)
        in_sh[t] = pack2(rowA[t], rowB[t]);
    __syncwarp();

    St s;
    s.is0 = (lane == 0);
    s.is31 = (lane == 31);
    s.lnext = (lane + 1) & 31;
    s.cA = pack2(-1.75f, -1.75f);
    s.cG = pack2(-0.025f, -0.025f);
    s.cC = pack2(COEF, COEF);
    {
        float w1 = -Wt[Wlen - 1];
        s.w1n = pack2(w1, w1);
    }
#pragma unroll
    for (int m = 0; m < 12; ++m) {
        float v = -Wt[Wlen - (12 * lane + m + 1)];   // -wr[12*lane+m+1]
        s.wrn[m] = pack2(v, v);
    }
#pragma unroll
    for (int j = 0; j < 12; ++j) s.M[j] = 0ull;

    // ---- step 0 (exact): V_prev=0 -> spike, Vpre=-70, Vnew=-90; delta_0 NOT scattered
    s.Vlo = -90.0f; s.Vhi = -90.0f; s.V2 = pack2(-90.0f, -90.0f);
    if (s.is0) trc_sh[0] = pack2(-90.0f, -90.0f);

    // ---- step 1 (exact): V1 = V + 0.005*(-V + I*40); spike=0; mem=0
    {
        float ix, iy; unpack2(in_sh[1], ix, iy);
        float vnl = s.Vlo + 0.005f * (-s.Vlo + ix * 40.0f);
        float vnh = s.Vhi + 0.005f * (-s.Vhi + iy * 40.0f);
        u64 d1 = pack2(vnl - s.Vlo, vnh - s.Vhi);
#pragma unroll
        for (int j = 0; j < 12; ++j)                 // scatter delta_1 (r = 1)
            s.M[j] = fma2(s.wrn[(j + 10) % 12], d1, s.M[j]);
        s.Vlo = vnl; s.Vhi = vnh; s.V2 = pack2(vnl, vnh);
        if (s.is0) trc_sh[1] = pack2(vnl, vnh);

        // memF for step 2: mem_2 = wr1*delta_1 only (negated weights)
        s.memF = fma2(s.w1n, d1, 0ull);
    }

    // ---- main loop: n = 2 .. 373, 31 iterations of 12 steps
#define BODY12(NB)                              \
    step<2>(s, in_sh, trc_sh, (NB) + 0);        \
    step<3>(s, in_sh, trc_sh, (NB) + 1);        \
    step<4>(s, in_sh, trc_sh, (NB) + 2);        \
    step<5>(s, in_sh, trc_sh, (NB) + 3);        \
    step<6>(s, in_sh, trc_sh, (NB) + 4);        \
    step<7>(s, in_sh, trc_sh, (NB) + 5);        \
    step<8>(s, in_sh, trc_sh, (NB) + 6);        \
    step<9>(s, in_sh, trc_sh, (NB) + 7);        \
    step<10>(s, in_sh, trc_sh, (NB) + 8);       \
    step<11>(s, in_sh, trc_sh, (NB) + 9);       \
    step<0>(s, in_sh, trc_sh, (NB) + 10);       \
    step<1>(s, in_sh, trc_sh, (NB) + 11);

    for (int nb = 2; nb <= T_STEPS - 22; nb += 12) {   // nb = 2,14,...,362
        BODY12(nb)
    }
    // ---- epilogue: n = 374..383
    step<2>(s, in_sh, trc_sh, 374);
    step<3>(s, in_sh, trc_sh, 375);
    step<4>(s, in_sh, trc_sh, 376);
    step<5>(s, in_sh, trc_sh, 377);
    step<6>(s, in_sh, trc_sh, 378);
    step<7>(s, in_sh, trc_sh, 379);
    step<8>(s, in_sh, trc_sh, 380);
    step<9>(s, in_sh, trc_sh, 381);
    step<10>(s, in_sh, trc_sh, 382);
    step<11>(s, in_sh, trc_sh, 383);
#undef BODY12

    __syncwarp();

    // ---- dump: trace directly; spikes derived from trace[t-1]
    const size_t baseA = (size_t)sA * T_STEPS;
    const size_t baseB = (size_t)sB * T_STEPS;
    const size_t off   = (size_t)S * T_STEPS;
    for (int t = lane; t < T_STEPS; t += 32) {
        float vx, vy; unpack2(trc_sh[t], vx, vy);
        out[off + baseA + t] = vx;
        out[off + baseB + t] = vy;
        float sl, sh;
        if (t == 0) { sl = 1.0f; sh = 1.0f; }   // V_prev = 0 > -50
        else {
            float px, py; unpack2(trc_sh[t - 1], px, py);
            sl = (px > -50.0f) ? 1.0f : 0.0f;
            sh = (py > -50.0f) ? 1.0f : 0.0f;
        }
        out[baseA + t] = sl;
        out[baseB + t] = sh;
    }
}

extern "C" void kernel_launch(void* const* d_in, const int* in_sizes, int n_in,
                              void* d_out, int out_size)
{
    const float* I  = (const float*)d_in[0];
    const float* Wt = (const float*)d_in[1];
    float* out = (float*)d_out;

    const int S    = in_sizes[0] / T_STEPS;
    const int Wlen = in_sizes[1];

    const float coef = (float)(pow(0.1, 0.15) * tgamma(2.0 - 0.15) / 0.5);

    const int pairs = S / 2;                 // S = 2048 -> 1024 warp-blocks
    flif_kernel<<<pairs, 32>>>(I, Wt, out, S, Wlen, coef);
}

// round 11
// speedup vs baseline: 1.2426x; 1.2426x over previous
#include <cuda_runtime.h>
#include <math.h>

// FLIF fractional LIF — round 11.
// Latency-bound regime identified: wall = 384 * T_step (per-warp serial chain),
// issue slots are NOT the binder. This round minimizes the chain:
//  - scatter the critical slot J1=(RR+1)%12 FIRST (its weight is always wrn[0]),
//  - software-pipeline BOTH shfls (consume + handoff) one step ahead, issued
//    immediately after that first FMA -> remaining 11 FMAs hide under SHFL lat,
//  - reset select precomputed from previous V (nr2), chain stays packed f32x2:
//    SHFL -> add2(vp) -> add2(vn) -> fma2(d) -> FMA(J1) -> SHFL   (~42 cyc).

#define T_STEPS 384
typedef unsigned long long u64;

__device__ __forceinline__ u64 pack2(float x, float y) {
    u64 r; asm("mov.b64 %0, {%1, %2};" : "=l"(r) : "f"(x), "f"(y)); return r;
}
__device__ __forceinline__ void unpack2(u64 a, float& x, float& y) {
    asm("mov.b64 {%0, %1}, %2;" : "=f"(x), "=f"(y) : "l"(a));
}
__device__ __forceinline__ u64 fma2(u64 a, u64 b, u64 c) {
    u64 d; asm("fma.rn.f32x2 %0, %1, %2, %3;" : "=l"(d) : "l"(a), "l"(b), "l"(c)); return d;
}
__device__ __forceinline__ u64 add2(u64 a, u64 b) {
    u64 d; asm("add.rn.f32x2 %0, %1, %2;" : "=l"(d) : "l"(a), "l"(b)); return d;
}

struct St {
    u64 M[12];      // negated-memory accumulators (cyclic by age)
    u64 wrn[12];    // wrn[m] = (-wr[12*lane+m+1]) packed both halves
    u64 cA, cG, cC; // (-1.75,-1.75), (-0.025,-0.025), (COEF,COEF)
    u64 neg1;       // (-1,-1)
    u64 V2;         // packed previous V
    u64 nr2;        // negated reset for CURRENT step: per half, (Vprev>-50)?-20:0
    u64 bcC;        // consume value for CURRENT step (lane0 slot, negated mem)
    u64 tmpH;       // handoff value for CURRENT step (lane+1 slot)
    bool is0, is31;
    int lnext;
};

// One uniform step for n >= 2.  RR = n % 12 (compile-time).
template<int RR>
__device__ __forceinline__ void step(St& s, const u64* __restrict__ inw,
                                     u64* __restrict__ trcw, int idx)
{
    constexpr int J1 = (RR + 1) % 12;

    // off-chain input path
    u64 a2 = add2(inw[idx], s.cA);            // In - 1.75
    u64 t2 = fma2(s.V2, s.cG, a2);            // -0.025*V + In - 1.75
    u64 u2 = fma2(t2, s.cC, s.V2);            // COEF*(...) + V

    // ---- critical chain ----
    u64 vp2 = add2(u2, s.bcC);                // minus memory (bcC negated)
    u64 vn2 = add2(vp2, s.nr2);               // minus reset  (nr2 in {0,-20})
    u64 d2  = fma2(s.V2, s.neg1, vn2);        // delta_n = Vnew - Vprev

    s.M[RR] = s.is31 ? 0ull : s.tmpH;         // tail refill (pipelined handoff)
    s.M[J1] = fma2(s.wrn[0], d2, s.M[J1]);    // FIRST scatter = next consume slot

    // pipelined shfls for step n+1 (slot J1), issued ASAP
    s.bcC  = __shfl_sync(0xffffffffu, s.M[J1], 0);
    s.tmpH = __shfl_sync(0xffffffffu, s.M[J1], s.lnext);

    // remaining 11 scatters execute in the shfl shadow
#pragma unroll
    for (int j = 0; j < 12; ++j)
        if (j != J1)
            s.M[j] = fma2(s.wrn[(j + 11 - RR) % 12], d2, s.M[j]);

    // off-chain epilogue: trc store + next reset from CURRENT Vnew
    float vnl, vnh; unpack2(vn2, vnl, vnh);
    if (s.is0) trcw[idx] = vn2;
    s.nr2 = pack2((vnl > -50.0f) ? -20.0f : 0.0f,
                  (vnh > -50.0f) ? -20.0f : 0.0f);
    s.V2 = vn2;
}

__global__ __launch_bounds__(32) void flif_kernel(
    const float* __restrict__ I,    // [S, T]
    const float* __restrict__ Wt,   // weights, length Wlen
    float* __restrict__ out,        // [2, S, T]: spikes then trace
    int S, int Wlen, float COEF)
{
    __shared__ u64 in_sh[T_STEPS];
    __shared__ u64 trc_sh[T_STEPS];

    const int lane = threadIdx.x & 31;
    const int pair = blockIdx.x;
    const int sA = pair * 2, sB = sA + 1;

    const float* rowA = I + (size_t)sA * T_STEPS;
    const float* rowB = I + (size_t)sB * T_STEPS;
    for (int t = lane; t < T_STEPS; t += 32)
        in_sh[t] = pack2(rowA[t], rowB[t]);
    __syncwarp();

    St s;
    s.is0 = (lane == 0);
    s.is31 = (lane == 31);
    s.lnext = (lane + 1) & 31;
    s.cA = pack2(-1.75f, -1.75f);
    s.cG = pack2(-0.025f, -0.025f);
    s.cC = pack2(COEF, COEF);
    s.neg1 = pack2(-1.0f, -1.0f);
#pragma unroll
    for (int m = 0; m < 12; ++m) {
        float v = -Wt[Wlen - (12 * lane + m + 1)];   // -wr[12*lane+m+1]
        s.wrn[m] = pack2(v, v);
    }
#pragma unroll
    for (int j = 0; j < 12; ++j) s.M[j] = 0ull;

    // ---- step 0 (exact): V_prev=0 -> spike, Vpre=-70, Vnew=-90; delta_0 NOT scattered
    float V0l = -90.0f, V0h = -90.0f;
    s.V2 = pack2(V0l, V0h);
    if (s.is0) trc_sh[0] = pack2(-90.0f, -90.0f);

    // ---- step 1 (exact): V1 = V + 0.005*(-V + I*40); spike=0 (V0=-90); mem=0
    {
        float ix, iy; unpack2(in_sh[1], ix, iy);
        float vnl = V0l + 0.005f * (-V0l + ix * 40.0f);
        float vnh = V0h + 0.005f * (-V0h + iy * 40.0f);
        u64 d1 = pack2(vnl - V0l, vnh - V0h);
#pragma unroll
        for (int j = 0; j < 12; ++j)                 // scatter delta_1 (r = 1)
            s.M[j] = fma2(s.wrn[(j + 10) % 12], d1, s.M[j]);
        s.V2 = pack2(vnl, vnh);
        if (s.is0) trc_sh[1] = pack2(vnl, vnh);

        // pipeline seed for uniform step n=2 (RR=2):
        s.bcC  = __shfl_sync(0xffffffffu, s.M[2], 0);        // mem_2 (negated)
        s.tmpH = __shfl_sync(0xffffffffu, s.M[2], s.lnext);  // handoff slot 2
        s.nr2  = pack2((vnl > -50.0f) ? -20.0f : 0.0f,       // reset for step 2
                       (vnh > -50.0f) ? -20.0f : 0.0f);
    }

    // ---- main loop: n = 2 .. 373, 31 iterations of 12 steps
#define BODY12(NB)                              \
    step<2>(s, in_sh, trc_sh, (NB) + 0);        \
    step<3>(s, in_sh, trc_sh, (NB) + 1);        \
    step<4>(s, in_sh, trc_sh, (NB) + 2);        \
    step<5>(s, in_sh, trc_sh, (NB) + 3);        \
    step<6>(s, in_sh, trc_sh, (NB) + 4);        \
    step<7>(s, in_sh, trc_sh, (NB) + 5);        \
    step<8>(s, in_sh, trc_sh, (NB) + 6);        \
    step<9>(s, in_sh, trc_sh, (NB) + 7);        \
    step<10>(s, in_sh, trc_sh, (NB) + 8);       \
    step<11>(s, in_sh, trc_sh, (NB) + 9);       \
    step<0>(s, in_sh, trc_sh, (NB) + 10);       \
    step<1>(s, in_sh, trc_sh, (NB) + 11);

    for (int nb = 2; nb <= T_STEPS - 22; nb += 12) {   // nb = 2,14,...,362
        BODY12(nb)
    }
    // ---- epilogue: n = 374..383
    step<2>(s, in_sh, trc_sh, 374);
    step<3>(s, in_sh, trc_sh, 375);
    step<4>(s, in_sh, trc_sh, 376);
    step<5>(s, in_sh, trc_sh, 377);
    step<6>(s, in_sh, trc_sh, 378);
    step<7>(s, in_sh, trc_sh, 379);
    step<8>(s, in_sh, trc_sh, 380);
    step<9>(s, in_sh, trc_sh, 381);
    step<10>(s, in_sh, trc_sh, 382);
    step<11>(s, in_sh, trc_sh, 383);
#undef BODY12

    __syncwarp();

    // ---- dump: trace directly; spikes derived from trace[t-1]
    const size_t baseA = (size_t)sA * T_STEPS;
    const size_t baseB = (size_t)sB * T_STEPS;
    const size_t off   = (size_t)S * T_STEPS;
    for (int t = lane; t < T_STEPS; t += 32) {
        float vx, vy; unpack2(trc_sh[t], vx, vy);
        out[off + baseA + t] = vx;
        out[off + baseB + t] = vy;
        float sl, sh;
        if (t == 0) { sl = 1.0f; sh = 1.0f; }   // V_prev = 0 > -50
        else {
            float px, py; unpack2(trc_sh[t - 1], px, py);
            sl = (px > -50.0f) ? 1.0f : 0.0f;
            sh = (py > -50.0f) ? 1.0f : 0.0f;
        }
        out[baseA + t] = sl;
        out[baseB + t] = sh;
    }
}

extern "C" void kernel_launch(void* const* d_in, const int* in_sizes, int n_in,
                              void* d_out, int out_size)
{
    const float* I  = (const float*)d_in[0];
    const float* Wt = (const float*)d_in[1];
    float* out = (float*)d_out;

    const int S    = in_sizes[0] / T_STEPS;
    const int Wlen = in_sizes[1];

    const float coef = (float)(pow(0.1, 0.15) * tgamma(2.0 - 0.15) / 0.5);

    const int pairs = S / 2;                 // S = 2048 -> 1024 warp-blocks
    flif_kernel<<<pairs, 32>>>(I, Wt, out, S, Wlen, coef);
}